// round 16
// baseline (speedup 1.0000x reference)
#include <cuda_runtime.h>
#include <cuda_fp16.h>
#include <math.h>
#include <stdint.h>

// Problem constants
#define Bn   32
#define DQ   512
#define DK   512
#define NK   16
#define Hn   8
#define Tt   12
#define Nn   207
#define Cc   64
#define TNC  (Tt*Nn*Cc)      // 158976
#define Mrows (Bn*NK)        // 512
#define Ncols (Hn*DQ)        // 4096
#define NXB  32              // col blocks (4096/128)
#define NYB  4               // row blocks (512/128)
#define NBLK (NXB*NYB)       // 128

__device__ __half g_Wh[Ncols * DK];    // fp16 W (4MB)
__device__ __half g_Xh[Mrows * DK];    // fp16 keys, transposed (512KB)
__device__ float  g_part[NXB * Mrows]; // per-colblock logits partials
__device__ float  g_att[Mrows];        // softmax weights
__device__ unsigned g_cnt = 0;         // completion counter (wraps mod NBLK)

// ---------------------------------------------------------------------------
__device__ __forceinline__ void mma_fp16(float* c, const uint32_t* a,
                                         uint32_t b0, uint32_t b1) {
    asm volatile(
        "mma.sync.aligned.m16n8k16.row.col.f32.f16.f16.f32 "
        "{%0,%1,%2,%3}, {%4,%5,%6,%7}, {%8,%9}, {%0,%1,%2,%3};"
        : "+f"(c[0]), "+f"(c[1]), "+f"(c[2]), "+f"(c[3])
        : "r"(a[0]), "r"(a[1]), "r"(a[2]), "r"(a[3]), "r"(b0), "r"(b1));
}

__device__ __forceinline__ void cp_async16(uint32_t smem_addr, const void* gptr) {
    asm volatile("cp.async.cg.shared.global [%0], [%1], 16;"
                 :: "r"(smem_addr), "l"(gptr));
}

// ---------------------------------------------------------------------------
// Kernel 0: blocks [0,2048): W -> fp16, 1 float4/thread (max parallelism,
// zero dependent chains, ~14 blk/SM single wave);
// blocks [2048,2304): keys -> fp16 transposed, smem-staged (proven).
// ---------------------------------------------------------------------------
__global__ __launch_bounds__(256)
void prep_kernel(const float* __restrict__ keys, const float* __restrict__ W,
                 __half* __restrict__ Xh, __half* __restrict__ Wh) {
    int bid = blockIdx.x;
    int tid = threadIdx.x;
    if (bid < 2048) {
        int i = bid * 256 + tid;                  // 524288 float4 total
        float4 v = ((const float4*)W)[i];
        ((__half2*)Wh)[i * 2]     = __floats2half2_rn(v.x, v.y);
        ((__half2*)Wh)[i * 2 + 1] = __floats2half2_rn(v.z, v.w);
    } else {
        __shared__ float s[64 * 17];
        int blk = bid - 2048;                     // 0..255
        int b  = blk >> 3;                        // 0..31
        int d0 = (blk & 7) * 64;                  // 0..448
        int dl = tid >> 2;                        // 0..63
        int c4 = tid & 3;                         // 0..3
        float4 v = ((const float4*)(keys + ((size_t)b * DK + d0 + dl) * NK))[c4];
        float* sr = &s[dl * 17 + 0];
        sr[c4 * 4 + 0] = v.x; sr[c4 * 4 + 1] = v.y;
        sr[c4 * 4 + 2] = v.z; sr[c4 * 4 + 3] = v.w;
        __syncthreads();
        int k  = tid >> 4;                        // 0..15
        int dq = (tid & 15) * 4;                  // 0..60
        __half2 h0 = __floats2half2_rn(s[(dq + 0) * 17 + k], s[(dq + 1) * 17 + k]);
        __half2 h1 = __floats2half2_rn(s[(dq + 2) * 17 + k], s[(dq + 3) * 17 + k]);
        __half2* dst = (__half2*)(Xh + (size_t)(b * NK + k) * DK + d0 + dq);
        dst[0] = h0; dst[1] = h1;
    }
}

// ---------------------------------------------------------------------------
// Kernel A: fp16 m16n8k16 GEMM + fused ReLU/bias/Q-dot + last-block softmax.
// (R13 config, measured ~6us.) PDL: grid-dep sync before touching Xh/Wh.
// ---------------------------------------------------------------------------
#define RSTR 36                    // row stride in u32 (64 halves + 8 pad)
#define TILE_U32 (128 * RSTR)      // 4608 u32 per tile
#define GEMM_SMEM_U32 (4*TILE_U32 + 1024 + 128 + 128 + 512)
#define GEMM_SMEM_BYTES (GEMM_SMEM_U32 * 4)

__global__ __launch_bounds__(256, 2)
void gemm_att_fp16(const __half* __restrict__ Xh, const __half* __restrict__ Wh,
                   const float* __restrict__ bias, const float* __restrict__ query,
                   float* __restrict__ part, float* __restrict__ att) {
    extern __shared__ uint32_t smem[];
    uint32_t* As = smem;                         // 2 stages x 4608
    uint32_t* Bs = As + 2 * TILE_U32;            // 2 stages x 4608
    float* Qs    = (float*)(Bs + 2 * TILE_U32);  // 8*128
    float* biasS = Qs + 8 * 128;                 // 128
    float* partS = biasS + 128;                  // 128
    float* redS  = partS + 128;                  // 512

    int tid  = threadIdx.x;
    int lane = tid & 31;
    int warp = tid >> 5;
    int warp_m = warp >> 2;        // 0..1
    int warp_n = warp & 3;         // 0..3
    int g   = lane >> 2;           // 0..7
    int tig = lane & 3;            // 0..3

    int c0 = blockIdx.x * 128;
    int m0 = blockIdx.y * 128;
    int q0 = c0 & (DQ - 1);
    int b0 = m0 >> 4;              // 8 batches per 128 rows

    uint32_t sA = (uint32_t)__cvta_generic_to_shared(As);
    uint32_t sB = (uint32_t)__cvta_generic_to_shared(Bs);

    // Stage Q/bias (independent of prep outputs) while prep finishes
    for (int i = tid; i < 8 * 128; i += 256)
        Qs[i] = query[(b0 + (i >> 7)) * DQ + q0 + (i & 127)];
    if (tid < 128) { biasS[tid] = bias[c0 + tid]; partS[tid] = 0.0f; }

    // wait for prep's Xh/Wh (no-op when launched without PDL)
    cudaGridDependencySynchronize();

    auto issue_tile = [&](int kt, int s) {
        uint32_t aBase = sA + (uint32_t)(s * TILE_U32) * 4;
        uint32_t bBase = sB + (uint32_t)(s * TILE_U32) * 4;
        #pragma unroll
        for (int i = 0; i < 4; i++) {
            int flat = i * 256 + tid;             // 0..1023
            int r  = flat >> 3;                   // 0..127
            int c8 = flat & 7;                    // 16B chunk (8 halves)
            cp_async16(aBase + (uint32_t)(r * RSTR + c8 * 4) * 4,
                       Xh + (size_t)(m0 + r) * DK + kt + c8 * 8);
        }
        #pragma unroll
        for (int i = 0; i < 4; i++) {
            int flat = i * 256 + tid;
            int r  = flat >> 3;
            int c8 = flat & 7;
            cp_async16(bBase + (uint32_t)(r * RSTR + c8 * 4) * 4,
                       Wh + (size_t)(c0 + r) * DK + kt + c8 * 8);
        }
        asm volatile("cp.async.commit_group;");
    };

    float acc[4][4][4] = {};
    issue_tile(0, 0);

    for (int it = 0; it < 8; it++) {
        int buf = it & 1;
        if (it < 7) {
            issue_tile((it + 1) * 64, buf ^ 1);
            asm volatile("cp.async.wait_group 1;");
        } else {
            asm volatile("cp.async.wait_group 0;");
        }
        __syncthreads();

        const uint32_t* Ab = As + buf * TILE_U32;
        const uint32_t* Bb = Bs + buf * TILE_U32;

        #pragma unroll
        for (int ks = 0; ks < 4; ks++) {          // 4 k16-steps per BK=64
            int k8 = ks * 8;
            uint32_t a[4][4];
            #pragma unroll
            for (int mt = 0; mt < 4; mt++) {
                int mb = warp_m * 64 + mt * 16 + g;
                const uint32_t* ar0 = &Ab[mb * RSTR + k8];
                const uint32_t* ar1 = &Ab[(mb + 8) * RSTR + k8];
                a[mt][0] = ar0[tig];
                a[mt][1] = ar1[tig];
                a[mt][2] = ar0[4 + tig];
                a[mt][3] = ar1[4 + tig];
            }
            #pragma unroll
            for (int nt = 0; nt < 4; nt++) {
                int nb = warp_n * 32 + nt * 8 + g;
                uint32_t b0r = Bb[nb * RSTR + k8 + tig];
                uint32_t b1r = Bb[nb * RSTR + k8 + 4 + tig];
                #pragma unroll
                for (int mt = 0; mt < 4; mt++)
                    mma_fp16(acc[mt][nt], a[mt], b0r, b1r);
            }
        }
        __syncthreads();
    }

    // Epilogue: bias + relu + Q-weight, reduce per row
    #pragma unroll
    for (int mt = 0; mt < 4; mt++) {
        int mlo = warp_m * 64 + mt * 16 + g;
        int mhi = mlo + 8;
        const float* q_lo = &Qs[(mlo >> 4) * 128];
        const float* q_hi = &Qs[(mhi >> 4) * 128];
        float p_lo = 0.0f, p_hi = 0.0f;
        #pragma unroll
        for (int nt = 0; nt < 4; nt++) {
            int cl = warp_n * 32 + nt * 8 + 2 * tig;
            float bi0 = biasS[cl], bi1 = biasS[cl + 1];
            p_lo = fmaf(fmaxf(acc[mt][nt][0] + bi0, 0.0f), q_lo[cl],     p_lo);
            p_lo = fmaf(fmaxf(acc[mt][nt][1] + bi1, 0.0f), q_lo[cl + 1], p_lo);
            p_hi = fmaf(fmaxf(acc[mt][nt][2] + bi0, 0.0f), q_hi[cl],     p_hi);
            p_hi = fmaf(fmaxf(acc[mt][nt][3] + bi1, 0.0f), q_hi[cl + 1], p_hi);
        }
        p_lo += __shfl_xor_sync(0xffffffffu, p_lo, 1);
        p_lo += __shfl_xor_sync(0xffffffffu, p_lo, 2);
        p_hi += __shfl_xor_sync(0xffffffffu, p_hi, 1);
        p_hi += __shfl_xor_sync(0xffffffffu, p_hi, 2);
        if (tig == 0) {
            atomicAdd(&partS[mlo], p_lo);
            atomicAdd(&partS[mhi], p_hi);
        }
    }
    __syncthreads();
    if (tid < 128) part[blockIdx.x * Mrows + m0 + tid] = partS[tid];

    // ---- last block: reduce partials + softmax ----
    __threadfence();
    __shared__ unsigned s_last;
    if (tid == 0) {
        unsigned old;
        asm volatile("atom.global.inc.u32 %0, [%1], %2;"
                     : "=r"(old) : "l"(&g_cnt), "r"((unsigned)(NBLK - 1)) : "memory");
        s_last = (old == NBLK - 1);
    }
    __syncthreads();
    if (!s_last) return;

    for (int m = tid; m < Mrows; m += 256) {
        float s = 0.0f;
        #pragma unroll
        for (int x = 0; x < NXB; x++) s += part[x * Mrows + m];
        redS[m] = s;
    }
    __syncthreads();
    if (tid < Bn) {
        const float scale = 1.0f / (8.0f * 22.62741699796952f);  // 1/(H*sqrt(512))
        float v[NK], mx = -1e30f;
        #pragma unroll
        for (int k = 0; k < NK; k++) { v[k] = redS[tid * NK + k] * scale; mx = fmaxf(mx, v[k]); }
        float z = 0.0f;
        #pragma unroll
        for (int k = 0; k < NK; k++) { v[k] = __expf(v[k] - mx); z += v[k]; }
        float inv = 1.0f / z;
        #pragma unroll
        for (int k = 0; k < NK; k++) att[tid * NK + k] = v[k] * inv;
    }
}

// ---------------------------------------------------------------------------
// Kernel C: att-weighted V reduction (R1 body). PDL: V loads issued BEFORE
// the grid-dep sync (V doesn't depend on GEMM) -> first wave prefetches
// during the GEMM tail. Grid exactly covers TNC (no early return).
// ---------------------------------------------------------------------------
__global__ __launch_bounds__(256)
void weighted_v_kernel(const float* __restrict__ V, const float* __restrict__ att,
                       float* __restrict__ out) {
    __shared__ float aw[NK];
    int b = blockIdx.y;
    int i = blockIdx.x * blockDim.x + threadIdx.x;   // grid*block == TNC exactly
    const float4* v4 = (const float4*)(V + ((size_t)b * TNC + i) * NK);
    float4 p0 = v4[0], p1 = v4[1], p2 = v4[2], p3 = v4[3];

    cudaGridDependencySynchronize();                 // att ready (no-op w/o PDL)
    if (threadIdx.x < NK) aw[threadIdx.x] = att[b * NK + threadIdx.x];
    __syncthreads();

    float s;
    s  = p0.x * aw[0]  + p0.y * aw[1]  + p0.z * aw[2]  + p0.w * aw[3];
    s += p1.x * aw[4]  + p1.y * aw[5]  + p1.z * aw[6]  + p1.w * aw[7];
    s += p2.x * aw[8]  + p2.y * aw[9]  + p2.z * aw[10] + p2.w * aw[11];
    s += p3.x * aw[12] + p3.y * aw[13] + p3.z * aw[14] + p3.w * aw[15];
    out[(size_t)b * TNC + i] = s;
}

// ---------------------------------------------------------------------------
extern "C" void kernel_launch(void* const* d_in, const int* in_sizes, int n_in,
                              void* d_out, int out_size) {
    const float *query = nullptr, *keys = nullptr, *V = nullptr,
                *W = nullptr, *bias = nullptr;
    for (int i = 0; i < n_in; i++) {
        switch (in_sizes[i]) {
            case Bn * DQ:            query = (const float*)d_in[i]; break;
            case Bn * DK * NK:       keys  = (const float*)d_in[i]; break;
            case Bn * TNC * NK:      V     = (const float*)d_in[i]; break;
            case Hn * DQ * DK:       W     = (const float*)d_in[i]; break;
            case Hn * DQ:            bias  = (const float*)d_in[i]; break;
            default: break;
        }
    }
    float* out = (float*)d_out;

    __half* Xh;  cudaGetSymbolAddress((void**)&Xh,  g_Xh);
    __half* Wh;  cudaGetSymbolAddress((void**)&Wh,  g_Wh);
    float* part; cudaGetSymbolAddress((void**)&part, g_part);
    float* att;  cudaGetSymbolAddress((void**)&att,  g_att);

    cudaFuncSetAttribute(gemm_att_fp16,
                         cudaFuncAttributeMaxDynamicSharedMemorySize,
                         GEMM_SMEM_BYTES);

    prep_kernel<<<2304, 256>>>(keys, W, Xh, Wh);

    // GEMM with PDL (falls back to plain launch if unsupported)
    {
        cudaLaunchAttribute attr[1];
        attr[0].id = cudaLaunchAttributeProgrammaticStreamSerialization;
        attr[0].val.programmaticStreamSerializationAllowed = 1;
        cudaLaunchConfig_t cfg = {};
        cfg.gridDim  = dim3(NXB, NYB);
        cfg.blockDim = dim3(256);
        cfg.dynamicSmemBytes = GEMM_SMEM_BYTES;
        cfg.stream = 0;
        cfg.attrs = attr;
        cfg.numAttrs = 1;
        if (cudaLaunchKernelEx(&cfg, gemm_att_fp16, Xh, (const __half*)Wh,
                               bias, query, part, att) != cudaSuccess) {
            gemm_att_fp16<<<dim3(NXB, NYB), 256, GEMM_SMEM_BYTES>>>(
                Xh, Wh, bias, query, part, att);
        }
    }

    // V with PDL (falls back to plain launch if unsupported)
    {
        cudaLaunchAttribute attr[1];
        attr[0].id = cudaLaunchAttributeProgrammaticStreamSerialization;
        attr[0].val.programmaticStreamSerializationAllowed = 1;
        cudaLaunchConfig_t cfg = {};
        cfg.gridDim  = dim3(TNC / 256, Bn);
        cfg.blockDim = dim3(256);
        cfg.dynamicSmemBytes = 0;
        cfg.stream = 0;
        cfg.attrs = attr;
        cfg.numAttrs = 1;
        if (cudaLaunchKernelEx(&cfg, weighted_v_kernel, (const float*)V,
                               (const float*)att, out) != cudaSuccess) {
            weighted_v_kernel<<<dim3(TNC / 256, Bn), 256>>>(V, att, out);
        }
    }
}

// round 17
// speedup vs baseline: 1.0286x; 1.0286x over previous
#include <cuda_runtime.h>
#include <cuda_fp16.h>
#include <math.h>
#include <stdint.h>

// Problem constants
#define Bn   32
#define DQ   512
#define DK   512
#define NK   16
#define Hn   8
#define Tt   12
#define Nn   207
#define Cc   64
#define TNC  (Tt*Nn*Cc)      // 158976
#define Mrows (Bn*NK)        // 512
#define Ncols (Hn*DQ)        // 4096
#define NXB  32              // col blocks (4096/128)
#define NYB  4               // row blocks (512/128)
#define NBLK (NXB*NYB)       // 128

__device__ __half g_Xh[Mrows * DK];    // fp16 keys, transposed (512KB)
__device__ float  g_part[NXB * Mrows]; // per-colblock logits partials
__device__ float  g_att[Mrows];        // softmax weights
__device__ unsigned g_cnt = 0;         // completion counter (wraps mod NBLK)

// ---------------------------------------------------------------------------
__device__ __forceinline__ void mma_fp16(float* c, const uint32_t* a,
                                         uint32_t b0, uint32_t b1) {
    asm volatile(
        "mma.sync.aligned.m16n8k16.row.col.f32.f16.f16.f32 "
        "{%0,%1,%2,%3}, {%4,%5,%6,%7}, {%8,%9}, {%0,%1,%2,%3};"
        : "+f"(c[0]), "+f"(c[1]), "+f"(c[2]), "+f"(c[3])
        : "r"(a[0]), "r"(a[1]), "r"(a[2]), "r"(a[3]), "r"(b0), "r"(b1));
}

__device__ __forceinline__ void cp_async16(uint32_t smem_addr, const void* gptr) {
    asm volatile("cp.async.cg.shared.global [%0], [%1], 16;"
                 :: "r"(smem_addr), "l"(gptr));
}

// ---------------------------------------------------------------------------
// Kernel 0: keys -> fp16 transposed ONLY (W conversion now fused into GEMM).
// 256 blocks, ~1.5us.
// ---------------------------------------------------------------------------
__global__ __launch_bounds__(256)
void prep_kernel(const float* __restrict__ keys, __half* __restrict__ Xh) {
    __shared__ float s[64 * 17];
    int blk = blockIdx.x;                     // 0..255
    int tid = threadIdx.x;
    int b  = blk >> 3;                        // 0..31
    int d0 = (blk & 7) * 64;                  // 0..448
    int dl = tid >> 2;                        // 0..63
    int c4 = tid & 3;                         // 0..3
    float4 v = ((const float4*)(keys + ((size_t)b * DK + d0 + dl) * NK))[c4];
    float* sr = &s[dl * 17 + 0];
    sr[c4 * 4 + 0] = v.x; sr[c4 * 4 + 1] = v.y;
    sr[c4 * 4 + 2] = v.z; sr[c4 * 4 + 3] = v.w;
    __syncthreads();
    int k  = tid >> 4;                        // 0..15
    int dq = (tid & 15) * 4;                  // 0..60
    __half2 h0 = __floats2half2_rn(s[(dq + 0) * 17 + k], s[(dq + 1) * 17 + k]);
    __half2 h1 = __floats2half2_rn(s[(dq + 2) * 17 + k], s[(dq + 3) * 17 + k]);
    __half2* dst = (__half2*)(Xh + (size_t)(b * NK + k) * DK + d0 + dq);
    dst[0] = h0; dst[1] = h1;
}

// ---------------------------------------------------------------------------
// Kernel A: fp16 m16n8k16 GEMM, W converted fp32->fp16 IN the B-path
// (LDG.128 one tile ahead -> register convert -> STS.64, conflict-free),
// A via cp.async from Xh; fused ReLU/bias/Q-dot + last-block softmax.
// BM=128, BN=128, BK=64; 256 threads; grid 128 blocks (1/SM) -> occ-1 bounds.
// ---------------------------------------------------------------------------
#define RSTR 36                    // row stride in u32 (64 halves + 8 pad)
#define TILE_U32 (128 * RSTR)      // 4608 u32 per tile
#define GEMM_SMEM_U32 (4*TILE_U32 + 1024 + 128 + 128 + 512)
#define GEMM_SMEM_BYTES (GEMM_SMEM_U32 * 4)

__global__ __launch_bounds__(256, 1)
void gemm_att_fp16(const __half* __restrict__ Xh, const float* __restrict__ W,
                   const float* __restrict__ bias, const float* __restrict__ query,
                   float* __restrict__ part, float* __restrict__ att) {
    extern __shared__ uint32_t smem[];
    uint32_t* As = smem;                         // 2 stages x 4608
    uint32_t* Bs = As + 2 * TILE_U32;            // 2 stages x 4608
    float* Qs    = (float*)(Bs + 2 * TILE_U32);  // 8*128
    float* biasS = Qs + 8 * 128;                 // 128
    float* partS = biasS + 128;                  // 128
    float* redS  = partS + 128;                  // 512

    int tid  = threadIdx.x;
    int lane = tid & 31;
    int warp = tid >> 5;
    int warp_m = warp >> 2;        // 0..1
    int warp_n = warp & 3;         // 0..3
    int g   = lane >> 2;           // 0..7
    int tig = lane & 3;            // 0..3

    int c0 = blockIdx.x * 128;
    int m0 = blockIdx.y * 128;
    int q0 = c0 & (DQ - 1);
    int b0 = m0 >> 4;              // 8 batches per 128 rows

    uint32_t sA = (uint32_t)__cvta_generic_to_shared(As);

    // B-path: thread's 8 chunks: flat = i*256+tid, r = flat>>4, c4 = flat&15
    int b_r  = tid >> 4;           // base row (stride 16 over i)
    int b_c4 = tid & 15;
    float4 bv[8];

    auto ldg_B = [&](int kt) {
        #pragma unroll
        for (int i = 0; i < 8; i++) {
            int r = b_r + i * 16;
            bv[i] = __ldg((const float4*)(W + (size_t)(c0 + r) * DK + kt) + b_c4);
        }
    };
    auto sts_B = [&](int s) {
        uint32_t* Bt = Bs + s * TILE_U32;
        #pragma unroll
        for (int i = 0; i < 8; i++) {
            int r = b_r + i * 16;
            __half2 h0 = __floats2half2_rn(bv[i].x, bv[i].y);
            __half2 h1 = __floats2half2_rn(bv[i].z, bv[i].w);
            uint2 val = make_uint2(*(uint32_t*)&h0, *(uint32_t*)&h1);
            *(uint2*)&Bt[r * RSTR + b_c4 * 2] = val;
        }
    };
    auto issue_A = [&](int kt, int s) {
        uint32_t aBase = sA + (uint32_t)(s * TILE_U32) * 4;
        #pragma unroll
        for (int i = 0; i < 4; i++) {
            int flat = i * 256 + tid;             // 0..1023
            int r  = flat >> 3;                   // 0..127
            int c8 = flat & 7;                    // 16B chunk (8 halves)
            cp_async16(aBase + (uint32_t)(r * RSTR + c8 * 4) * 4,
                       Xh + (size_t)(m0 + r) * DK + kt + c8 * 8);
        }
        asm volatile("cp.async.commit_group;");
    };

    // ---- independent of prep: Q/bias staging + B tile0/1 loads ----
    for (int i = tid; i < 8 * 128; i += 256)
        Qs[i] = query[(b0 + (i >> 7)) * DQ + q0 + (i & 127)];
    if (tid < 128) { biasS[tid] = bias[c0 + tid]; partS[tid] = 0.0f; }

    ldg_B(0);
    sts_B(0);                      // tile0 fp16 in stage 0
    ldg_B(64);                     // tile1 held in registers

    // wait for prep's Xh (no-op when launched without PDL)
    cudaGridDependencySynchronize();

    issue_A(0, 0);

    float acc[4][4][4] = {};

    for (int it = 0; it < 8; it++) {
        int s = it & 1;
        if (it < 7) {
            issue_A((it + 1) * 64, s ^ 1);
            asm volatile("cp.async.wait_group 1;");
        } else {
            asm volatile("cp.async.wait_group 0;");
        }
        __syncthreads();           // A_it + B_it visible

        const uint32_t* Ab = As + s * TILE_U32;
        const uint32_t* Bb = Bs + s * TILE_U32;

        #pragma unroll
        for (int ks = 0; ks < 4; ks++) {          // 4 k16-steps per BK=64
            int k8 = ks * 8;
            uint32_t a[4][4];
            #pragma unroll
            for (int mt = 0; mt < 4; mt++) {
                int mb = warp_m * 64 + mt * 16 + g;
                const uint32_t* ar0 = &Ab[mb * RSTR + k8];
                const uint32_t* ar1 = &Ab[(mb + 8) * RSTR + k8];
                a[mt][0] = ar0[tig];
                a[mt][1] = ar1[tig];
                a[mt][2] = ar0[4 + tig];
                a[mt][3] = ar1[4 + tig];
            }
            #pragma unroll
            for (int nt = 0; nt < 4; nt++) {
                int nb = warp_n * 32 + nt * 8 + g;
                uint32_t b0r = Bb[nb * RSTR + k8 + tig];
                uint32_t b1r = Bb[nb * RSTR + k8 + 4 + tig];
                #pragma unroll
                for (int mt = 0; mt < 4; mt++)
                    mma_fp16(acc[mt][nt], a[mt], b0r, b1r);
            }
        }

        // convert+store B_{it+1} (regs), then prefetch B_{it+2}
        if (it < 7) {
            sts_B(s ^ 1);
            if (it < 6) ldg_B((it + 2) * 64);
        }
        __syncthreads();           // B_{it+1} visible; stage s safe for reuse
    }

    // Epilogue: bias + relu + Q-weight, reduce per row
    #pragma unroll
    for (int mt = 0; mt < 4; mt++) {
        int mlo = warp_m * 64 + mt * 16 + g;
        int mhi = mlo + 8;
        const float* q_lo = &Qs[(mlo >> 4) * 128];
        const float* q_hi = &Qs[(mhi >> 4) * 128];
        float p_lo = 0.0f, p_hi = 0.0f;
        #pragma unroll
        for (int nt = 0; nt < 4; nt++) {
            int cl = warp_n * 32 + nt * 8 + 2 * tig;
            float bi0 = biasS[cl], bi1 = biasS[cl + 1];
            p_lo = fmaf(fmaxf(acc[mt][nt][0] + bi0, 0.0f), q_lo[cl],     p_lo);
            p_lo = fmaf(fmaxf(acc[mt][nt][1] + bi1, 0.0f), q_lo[cl + 1], p_lo);
            p_hi = fmaf(fmaxf(acc[mt][nt][2] + bi0, 0.0f), q_hi[cl],     p_hi);
            p_hi = fmaf(fmaxf(acc[mt][nt][3] + bi1, 0.0f), q_hi[cl + 1], p_hi);
        }
        p_lo += __shfl_xor_sync(0xffffffffu, p_lo, 1);
        p_lo += __shfl_xor_sync(0xffffffffu, p_lo, 2);
        p_hi += __shfl_xor_sync(0xffffffffu, p_hi, 1);
        p_hi += __shfl_xor_sync(0xffffffffu, p_hi, 2);
        if (tig == 0) {
            atomicAdd(&partS[mlo], p_lo);
            atomicAdd(&partS[mhi], p_hi);
        }
    }
    __syncthreads();
    if (tid < 128) part[blockIdx.x * Mrows + m0 + tid] = partS[tid];

    // ---- last block: reduce partials + softmax ----
    __threadfence();
    __shared__ unsigned s_last;
    if (tid == 0) {
        unsigned old;
        asm volatile("atom.global.inc.u32 %0, [%1], %2;"
                     : "=r"(old) : "l"(&g_cnt), "r"((unsigned)(NBLK - 1)) : "memory");
        s_last = (old == NBLK - 1);
    }
    __syncthreads();
    if (!s_last) return;

    for (int m = tid; m < Mrows; m += 256) {
        float s = 0.0f;
        #pragma unroll
        for (int x = 0; x < NXB; x++) s += part[x * Mrows + m];
        redS[m] = s;
    }
    __syncthreads();
    if (tid < Bn) {
        const float scale = 1.0f / (8.0f * 22.62741699796952f);  // 1/(H*sqrt(512))
        float v[NK], mx = -1e30f;
        #pragma unroll
        for (int k = 0; k < NK; k++) { v[k] = redS[tid * NK + k] * scale; mx = fmaxf(mx, v[k]); }
        float z = 0.0f;
        #pragma unroll
        for (int k = 0; k < NK; k++) { v[k] = __expf(v[k] - mx); z += v[k]; }
        float inv = 1.0f / z;
        #pragma unroll
        for (int k = 0; k < NK; k++) att[tid * NK + k] = v[k] * inv;
    }
}

// ---------------------------------------------------------------------------
// Kernel C: att-weighted V reduction (R1 body). PDL: V loads issued BEFORE
// the grid-dep sync. Grid exactly covers TNC (no early return).
// ---------------------------------------------------------------------------
__global__ __launch_bounds__(256)
void weighted_v_kernel(const float* __restrict__ V, const float* __restrict__ att,
                       float* __restrict__ out) {
    __shared__ float aw[NK];
    int b = blockIdx.y;
    int i = blockIdx.x * blockDim.x + threadIdx.x;   // grid*block == TNC exactly
    const float4* v4 = (const float4*)(V + ((size_t)b * TNC + i) * NK);
    float4 p0 = v4[0], p1 = v4[1], p2 = v4[2], p3 = v4[3];

    cudaGridDependencySynchronize();                 // att ready (no-op w/o PDL)
    if (threadIdx.x < NK) aw[threadIdx.x] = att[b * NK + threadIdx.x];
    __syncthreads();

    float s;
    s  = p0.x * aw[0]  + p0.y * aw[1]  + p0.z * aw[2]  + p0.w * aw[3];
    s += p1.x * aw[4]  + p1.y * aw[5]  + p1.z * aw[6]  + p1.w * aw[7];
    s += p2.x * aw[8]  + p2.y * aw[9]  + p2.z * aw[10] + p2.w * aw[11];
    s += p3.x * aw[12] + p3.y * aw[13] + p3.z * aw[14] + p3.w * aw[15];
    out[(size_t)b * TNC + i] = s;
}

// ---------------------------------------------------------------------------
extern "C" void kernel_launch(void* const* d_in, const int* in_sizes, int n_in,
                              void* d_out, int out_size) {
    const float *query = nullptr, *keys = nullptr, *V = nullptr,
                *W = nullptr, *bias = nullptr;
    for (int i = 0; i < n_in; i++) {
        switch (in_sizes[i]) {
            case Bn * DQ:            query = (const float*)d_in[i]; break;
            case Bn * DK * NK:       keys  = (const float*)d_in[i]; break;
            case Bn * TNC * NK:      V     = (const float*)d_in[i]; break;
            case Hn * DQ * DK:       W     = (const float*)d_in[i]; break;
            case Hn * DQ:            bias  = (const float*)d_in[i]; break;
            default: break;
        }
    }
    float* out = (float*)d_out;

    __half* Xh;  cudaGetSymbolAddress((void**)&Xh,  g_Xh);
    float* part; cudaGetSymbolAddress((void**)&part, g_part);
    float* att;  cudaGetSymbolAddress((void**)&att,  g_att);

    cudaFuncSetAttribute(gemm_att_fp16,
                         cudaFuncAttributeMaxDynamicSharedMemorySize,
                         GEMM_SMEM_BYTES);

    prep_kernel<<<256, 256>>>(keys, Xh);

    // GEMM with PDL (falls back to plain launch if unsupported)
    {
        cudaLaunchAttribute attr[1];
        attr[0].id = cudaLaunchAttributeProgrammaticStreamSerialization;
        attr[0].val.programmaticStreamSerializationAllowed = 1;
        cudaLaunchConfig_t cfg = {};
        cfg.gridDim  = dim3(NXB, NYB);
        cfg.blockDim = dim3(256);
        cfg.dynamicSmemBytes = GEMM_SMEM_BYTES;
        cfg.stream = 0;
        cfg.attrs = attr;
        cfg.numAttrs = 1;
        if (cudaLaunchKernelEx(&cfg, gemm_att_fp16, (const __half*)Xh, W,
                               bias, query, part, att) != cudaSuccess) {
            gemm_att_fp16<<<dim3(NXB, NYB), 256, GEMM_SMEM_BYTES>>>(
                Xh, W, bias, query, part, att);
        }
    }

    // V with PDL (falls back to plain launch if unsupported)
    {
        cudaLaunchAttribute attr[1];
        attr[0].id = cudaLaunchAttributeProgrammaticStreamSerialization;
        attr[0].val.programmaticStreamSerializationAllowed = 1;
        cudaLaunchConfig_t cfg = {};
        cfg.gridDim  = dim3(TNC / 256, Bn);
        cfg.blockDim = dim3(256);
        cfg.dynamicSmemBytes = 0;
        cfg.stream = 0;
        cfg.attrs = attr;
        cfg.numAttrs = 1;
        if (cudaLaunchKernelEx(&cfg, weighted_v_kernel, (const float*)V,
                               (const float*)att, out) != cudaSuccess) {
            weighted_v_kernel<<<dim3(TNC / 256, Bn), 256>>>(V, att, out);
        }
    }
}